// round 1
// baseline (speedup 1.0000x reference)
#include <cuda_runtime.h>
#include <math.h>

#define BATCH 8
#define NA 49104
#define NC 80
#define KPRE 256
#define CAP 12288
#define CCAP 2048
#define MAXT 100
#define NEGV -1000000000.0f

// ---------------- device scratch (no allocations allowed) ----------------
__device__ unsigned long long g_cand[(size_t)BATCH * NC * CAP]; // ~63 MB
__device__ int   g_cnt[BATCH * NC];
__device__ float g_mscore[BATCH * NC * KPRE];
__device__ float4 g_mbox[BATCH * NC * KPRE];

// ---------------- K0: zero per-(b,c) candidate counters ----------------
__global__ void k_zero() {
    int t = blockIdx.x * blockDim.x + threadIdx.x;
    if (t < BATCH * NC) g_cnt[t] = 0;
}

// ---------------- K1: filter + append candidates ----------------
__device__ __forceinline__ void tryAppend(float x, int b, int c, unsigned a) {
    // sigmoid(x) > 0.05  <=>  x > log(0.05/0.95) ~= -2.9444; prefilter slightly wide
    if (x > -2.95f) {
        float s = 1.0f / (1.0f + expf(-x));
        if (s > 0.05f) {
            int li = b * NC + c;
            int pos = atomicAdd(&g_cnt[li], 1);
            if (pos < CAP) {
                unsigned long long key =
                    ((unsigned long long)__float_as_uint(s) << 32) |
                    (unsigned long long)(0xFFFFFFFFu - a);
                g_cand[(size_t)li * CAP + pos] = key;
            }
        }
    }
}

__global__ void __launch_bounds__(256) k_filter(const float* __restrict__ ycls) {
    long long t = (long long)blockIdx.x * blockDim.x + threadIdx.x;
    const long long total4 = (long long)BATCH * NA * NC / 4;
    if (t >= total4) return;
    float4 v = reinterpret_cast<const float4*>(ycls)[t];
    long long e = t * 4;
    int c = (int)(e % NC);          // NC % 4 == 0 -> 4 consecutive classes, same (b,a)
    long long ba = e / NC;
    int b = (int)(ba / NA);
    unsigned a = (unsigned)(ba % NA);
    tryAppend(v.x, b, c + 0, a);
    tryAppend(v.y, b, c + 1, a);
    tryAppend(v.z, b, c + 2, a);
    tryAppend(v.w, b, c + 3, a);
}

// ---------------- K2: per-(b,c) exact top-256 + greedy NMS ----------------
// dynamic smem layout:
//   [0      , 16384) cand   (2048 x u64)
//   [16384  , 32768) hist   (4096 x u32)   -- reused later for IoU masks (8 KB)
//   [32768  , 34816) chunk  (512 x u32)
//   [34816  , 40960) by1,bx1,by2,bx2,bar,bsc (6 x 256 f32)
#define K2_SMEM 40960

__global__ void __launch_bounds__(512) k_classnms(const float* __restrict__ ybbox,
                                                  const float* __restrict__ anchors) {
    extern __shared__ unsigned char smem_raw[];
    unsigned long long* cand = (unsigned long long*)smem_raw;
    unsigned int* hist  = (unsigned int*)(smem_raw + 16384);
    unsigned int* chunk = (unsigned int*)(smem_raw + 32768);
    float* by1 = (float*)(smem_raw + 34816);
    float* bx1 = by1 + 256; float* by2 = bx1 + 256; float* bx2 = by2 + 256;
    float* bar = bx2 + 256; float* bsc = bar + 256;
    unsigned int* masks = (unsigned int*)(smem_raw + 16384); // overlaps hist (dead by then)

    __shared__ int s_cb, s_sure, s_cnt;
    __shared__ unsigned int s_keep[8];

    int tid = threadIdx.x, nt = blockDim.x;
    int c = blockIdx.x, b = blockIdx.y;
    int li = b * NC + c;
    int n = g_cnt[li]; if (n > CAP) n = CAP;
    const unsigned long long* list = g_cand + (size_t)li * CAP;

    // --- level-1 histogram on top 12 bits of score float ---
    for (int i = tid; i < 4096; i += nt) hist[i] = 0;
    __syncthreads();
    for (int i = tid; i < n; i += nt)
        atomicAdd(&hist[(unsigned)(list[i] >> 52)], 1u);
    __syncthreads();
    if (tid < 512) {
        unsigned s = 0; int base = tid * 8;
        #pragma unroll
        for (int k = 0; k < 8; ++k) s += hist[base + k];
        chunk[tid] = s;
    }
    __syncthreads();
    if (tid == 0) {
        int acc = 0, cb = 0, sure = 0;
        for (int ch = 511; ch >= 0; --ch) {
            unsigned cs = chunk[ch];
            if (acc + (int)cs < KPRE) { acc += (int)cs; continue; }
            for (int bin = ch * 8 + 7;; --bin) {
                unsigned h = hist[bin];
                if (acc + (int)h >= KPRE) { cb = bin; sure = acc; break; }
                acc += (int)h;
            }
            break;
        }
        s_cb = cb; s_sure = sure; s_cnt = 0;
    }
    __syncthreads();
    int cb = s_cb;
    for (int i = tid; i < n; i += nt) {
        unsigned long long key = list[i];
        if ((int)(unsigned)(key >> 52) >= cb) {
            int pos = atomicAdd(&s_cnt, 1);
            if (pos < CCAP) cand[pos] = key;
        }
    }
    __syncthreads();

    if (s_cnt > CCAP) {   // refine inside boundary bin (statistically never for this data)
        int sure = s_sure;
        for (int i = tid; i < 4096; i += nt) hist[i] = 0;
        __syncthreads();
        for (int i = tid; i < n; i += nt) {
            unsigned long long key = list[i];
            if ((int)(unsigned)(key >> 52) == cb)
                atomicAdd(&hist[(unsigned)(key >> 40) & 0xFFFu], 1u);
        }
        __syncthreads();
        if (tid < 512) {
            unsigned s = 0; int base = tid * 8;
            #pragma unroll
            for (int k = 0; k < 8; ++k) s += hist[base + k];
            chunk[tid] = s;
        }
        __syncthreads();
        if (tid == 0) {
            int need = KPRE - sure; if (need < 1) need = 1;
            int acc = 0, cb2 = 0;
            for (int ch = 511; ch >= 0; --ch) {
                unsigned cs = chunk[ch];
                if (acc + (int)cs < need) { acc += (int)cs; continue; }
                for (int bin = ch * 8 + 7;; --bin) {
                    unsigned h = hist[bin];
                    if (acc + (int)h >= need) { cb2 = bin; break; }
                    acc += (int)h;
                }
                break;
            }
            s_cb = cb2; s_cnt = 0;
        }
        __syncthreads();
        int cb2 = s_cb;
        for (int i = tid; i < n; i += nt) {
            unsigned long long key = list[i];
            int bin = (int)(unsigned)(key >> 52);
            if (bin > cb || (bin == cb && (int)((unsigned)(key >> 40) & 0xFFFu) >= cb2)) {
                int pos = atomicAdd(&s_cnt, 1);
                if (pos < CCAP) cand[pos] = key;
            }
        }
        __syncthreads();
    }

    int total = min(s_cnt, CCAP);
    // --- bitonic sort descending on (score, ~anchor) keys ---
    if (total > 1) {
        int n2 = 1; while (n2 < total) n2 <<= 1;
        for (int i = tid; i < n2; i += nt) if (i >= total) cand[i] = 0ull;
        __syncthreads();
        for (int k = 2; k <= n2; k <<= 1)
            for (int j = k >> 1; j > 0; j >>= 1) {
                for (int i = tid; i < n2; i += nt) {
                    int ixj = i ^ j;
                    if (ixj > i) {
                        unsigned long long x = cand[i], y = cand[ixj];
                        bool up = ((i & k) == 0);
                        if (up ? (x < y) : (x > y)) { cand[i] = y; cand[ixj] = x; }
                    }
                }
                __syncthreads();
            }
    }
    int m = min(total, KPRE);

    // --- decode boxes for top-m ---
    for (int r = tid; r < m; r += nt) {
        unsigned long long key = cand[r];
        unsigned a = 0xFFFFFFFFu - (unsigned)(key & 0xFFFFFFFFull);
        float sc = __uint_as_float((unsigned)(key >> 32));
        float4 an  = reinterpret_cast<const float4*>(anchors)[a];
        float4 rel = reinterpret_cast<const float4*>(ybbox)[(size_t)b * NA + a];
        float ha = an.z - an.x, wa = an.w - an.y;
        float cya = an.x + 0.5f * ha, cxa = an.y + 0.5f * wa;
        float cy = cya + rel.x * ha, cx = cxa + rel.y * wa;
        float h = ha * expf(rel.z), w = wa * expf(rel.w);
        float y1 = cy - 0.5f * h, x1 = cx - 0.5f * w;
        float y2 = cy + 0.5f * h, x2 = cx + 0.5f * w;
        by1[r] = y1; bx1[r] = x1; by2[r] = y2; bx2[r] = x2;
        bar[r] = (y2 - y1) * (x2 - x1);
        bsc[r] = sc;
    }
    __syncthreads();

    // --- parallel IoU bitmask build (j > i only) ---
    for (int idx = tid; idx < m * 8; idx += nt) {
        int i = idx >> 3, w = idx & 7;
        float iy1 = by1[i], ix1 = bx1[i], iy2 = by2[i], ix2 = bx2[i], ia = bar[i];
        unsigned bits = 0;
        int j0 = w * 32;
        #pragma unroll 4
        for (int q = 0; q < 32; ++q) {
            int j = j0 + q;
            if (j > i && j < m) {
                float ih = fmaxf(fminf(iy2, by2[j]) - fmaxf(iy1, by1[j]), 0.0f);
                float iw = fmaxf(fminf(ix2, bx2[j]) - fmaxf(ix1, bx1[j]), 0.0f);
                float inter = ih * iw;
                float iou = inter / (ia + bar[j] - inter + 1e-8f);
                if (iou > 0.5f) bits |= (1u << q);
            }
        }
        masks[i * 8 + w] = bits;
    }
    __syncthreads();

    // --- serial greedy walk (thread 0), cap 100 keeps, suppression uncapped ---
    if (tid == 0) {
        unsigned rem[8] = {0,0,0,0,0,0,0,0};
        unsigned kp[8]  = {0,0,0,0,0,0,0,0};
        int cnt = 0;
        for (int i = 0; i < m; ++i) {
            if (!((rem[i >> 5] >> (i & 31)) & 1u)) {
                if (cnt < MAXT) kp[i >> 5] |= (1u << (i & 31));
                cnt++;
                #pragma unroll
                for (int w = 0; w < 8; ++w) rem[w] |= masks[i * 8 + w];
            }
        }
        #pragma unroll
        for (int w = 0; w < 8; ++w) s_keep[w] = kp[w];
    }
    __syncthreads();

    // --- write masked score + box per slot ---
    for (int r = tid; r < KPRE; r += nt) {
        int o = li * KPRE + r;
        bool kept = (r < m) && ((s_keep[r >> 5] >> (r & 31)) & 1u);
        g_mscore[o] = kept ? bsc[r] : NEGV;
        g_mbox[o] = (r < m) ? make_float4(by1[r], bx1[r], by2[r], bx2[r])
                            : make_float4(0.f, 0.f, 0.f, 0.f);
    }
}

// ---------------- K3: per-batch top-100 + NMS@0.7 + stable partition ----------------
// dynamic smem layout:
//   [0      , 16384) cand (2048 x u64)
//   [16384  , 32768) hist (4096 x u32) -- later reused: masks (2 KB) + src (0.5 KB)
//   [32768  , 34816) chunk
//   [34816  , 38400) ry1,rx1,ry2,rx2,rar,rsc,rcl (7 x 128 f32)
#define K3_SMEM 38400

__global__ void __launch_bounds__(512) k_final(const int* __restrict__ ohs,
                                               const int* __restrict__ ows,
                                               float* __restrict__ out) {
    extern __shared__ unsigned char smem_raw[];
    unsigned long long* cand = (unsigned long long*)smem_raw;
    unsigned int* hist  = (unsigned int*)(smem_raw + 16384);
    unsigned int* chunk = (unsigned int*)(smem_raw + 32768);
    float* ry1 = (float*)(smem_raw + 34816);
    float* rx1 = ry1 + 128; float* ry2 = rx1 + 128; float* rx2 = ry2 + 128;
    float* rar = rx2 + 128; float* rsc = rar + 128; float* rcl = rsc + 128;
    unsigned int* masks = (unsigned int*)(smem_raw + 16384);        // 128*4 u32
    int* src = (int*)(smem_raw + 16384 + 2048);                     // 128 ints

    __shared__ int s_cb, s_sure, s_cnt, s_nv;
    __shared__ unsigned int s_keep[4];

    int tid = threadIdx.x, nt = blockDim.x;
    int b = blockIdx.x;
    const int N = NC * KPRE;
    const float* msc = g_mscore + (size_t)b * N;

    for (int i = tid; i < 4096; i += nt) hist[i] = 0;
    __syncthreads();
    for (int i = tid; i < N; i += nt) {
        float s = msc[i];
        if (s > NEGV * 0.5f) atomicAdd(&hist[__float_as_uint(s) >> 20], 1u);
    }
    __syncthreads();
    if (tid < 512) {
        unsigned s = 0; int base = tid * 8;
        #pragma unroll
        for (int k = 0; k < 8; ++k) s += hist[base + k];
        chunk[tid] = s;
    }
    __syncthreads();
    if (tid == 0) {
        int acc = 0, cb = 0, sure = 0;
        for (int ch = 511; ch >= 0; --ch) {
            unsigned cs = chunk[ch];
            if (acc + (int)cs < MAXT) { acc += (int)cs; continue; }
            for (int bin = ch * 8 + 7;; --bin) {
                unsigned h = hist[bin];
                if (acc + (int)h >= MAXT) { cb = bin; sure = acc; break; }
                acc += (int)h;
            }
            break;
        }
        s_cb = cb; s_sure = sure; s_cnt = 0;
    }
    __syncthreads();
    int cb = s_cb;
    for (int i = tid; i < N; i += nt) {
        float s = msc[i];
        if (s > NEGV * 0.5f) {
            unsigned sb = __float_as_uint(s);
            if ((int)(sb >> 20) >= cb) {
                int pos = atomicAdd(&s_cnt, 1);
                if (pos < CCAP)
                    cand[pos] = ((unsigned long long)sb << 32) |
                                (unsigned long long)(0xFFFFFFFFu - (unsigned)i);
            }
        }
    }
    __syncthreads();
    if (s_cnt > CCAP) {   // refine (statistically never)
        int sure = s_sure;
        for (int i = tid; i < 4096; i += nt) hist[i] = 0;
        __syncthreads();
        for (int i = tid; i < N; i += nt) {
            float s = msc[i];
            if (s > NEGV * 0.5f) {
                unsigned sb = __float_as_uint(s);
                if ((int)(sb >> 20) == cb) atomicAdd(&hist[(sb >> 8) & 0xFFFu], 1u);
            }
        }
        __syncthreads();
        if (tid < 512) {
            unsigned s = 0; int base = tid * 8;
            #pragma unroll
            for (int k = 0; k < 8; ++k) s += hist[base + k];
            chunk[tid] = s;
        }
        __syncthreads();
        if (tid == 0) {
            int need = MAXT - sure; if (need < 1) need = 1;
            int acc = 0, cb2 = 0;
            for (int ch = 511; ch >= 0; --ch) {
                unsigned cs = chunk[ch];
                if (acc + (int)cs < need) { acc += (int)cs; continue; }
                for (int bin = ch * 8 + 7;; --bin) {
                    unsigned h = hist[bin];
                    if (acc + (int)h >= need) { cb2 = bin; break; }
                    acc += (int)h;
                }
                break;
            }
            s_cb = cb2; s_cnt = 0;
        }
        __syncthreads();
        int cb2 = s_cb;
        for (int i = tid; i < N; i += nt) {
            float s = msc[i];
            if (s > NEGV * 0.5f) {
                unsigned sb = __float_as_uint(s);
                int bin = (int)(sb >> 20);
                if (bin > cb || (bin == cb && (int)((sb >> 8) & 0xFFFu) >= cb2)) {
                    int pos = atomicAdd(&s_cnt, 1);
                    if (pos < CCAP)
                        cand[pos] = ((unsigned long long)sb << 32) |
                                    (unsigned long long)(0xFFFFFFFFu - (unsigned)i);
                }
            }
        }
        __syncthreads();
    }

    int total = min(s_cnt, CCAP);
    if (total > 1) {
        int n2 = 1; while (n2 < total) n2 <<= 1;
        for (int i = tid; i < n2; i += nt) if (i >= total) cand[i] = 0ull;
        __syncthreads();
        for (int k = 2; k <= n2; k <<= 1)
            for (int j = k >> 1; j > 0; j >>= 1) {
                for (int i = tid; i < n2; i += nt) {
                    int ixj = i ^ j;
                    if (ixj > i) {
                        unsigned long long x = cand[i], y = cand[ixj];
                        bool up = ((i & k) == 0);
                        if (up ? (x < y) : (x > y)) { cand[i] = y; cand[ixj] = x; }
                    }
                }
                __syncthreads();
            }
    }
    int nsel = min(total, MAXT);

    float fh = (float)ohs[b], fw = (float)ows[b];
    float rh = fh / 512.0f, rw = fw / 512.0f;
    for (int r = tid; r < nsel; r += nt) {
        unsigned long long key = cand[r];
        unsigned flat = 0xFFFFFFFFu - (unsigned)(key & 0xFFFFFFFFull);
        float sc = __uint_as_float((unsigned)(key >> 32));
        float4 bx = g_mbox[(size_t)b * N + flat];
        float y1 = fminf(fmaxf(bx.x * rh, 0.0f), fh);
        float x1 = fminf(fmaxf(bx.y * rw, 0.0f), fw);
        float y2 = fminf(fmaxf(bx.z * rh, 0.0f), fh);
        float x2 = fminf(fmaxf(bx.w * rw, 0.0f), fw);
        ry1[r] = y1; rx1[r] = x1; ry2[r] = y2; rx2[r] = x2;
        rar[r] = (y2 - y1) * (x2 - x1);
        rsc[r] = sc;
        rcl[r] = (float)(flat >> 8);   // flat = class*256 + rank
    }
    __syncthreads();

    for (int idx = tid; idx < nsel * 4; idx += nt) {
        int i = idx >> 2, w = idx & 3;
        float iy1 = ry1[i], ix1 = rx1[i], iy2 = ry2[i], ix2 = rx2[i], ia = rar[i];
        unsigned bits = 0;
        int j0 = w * 32;
        #pragma unroll 4
        for (int q = 0; q < 32; ++q) {
            int j = j0 + q;
            if (j > i && j < nsel) {
                float ih = fmaxf(fminf(iy2, ry2[j]) - fmaxf(iy1, ry1[j]), 0.0f);
                float iw = fmaxf(fminf(ix2, rx2[j]) - fmaxf(ix1, rx1[j]), 0.0f);
                float inter = ih * iw;
                float iou = inter / (ia + rar[j] - inter + 1e-8f);
                if (iou > 0.7f) bits |= (1u << q);
            }
        }
        masks[i * 4 + w] = bits;
    }
    __syncthreads();
    if (tid == 0) {
        unsigned rem[4] = {0,0,0,0}, kp[4] = {0,0,0,0};
        int cnt = 0;
        for (int i = 0; i < nsel; ++i) {
            if (!((rem[i >> 5] >> (i & 31)) & 1u)) {
                kp[i >> 5] |= (1u << (i & 31));
                cnt++;
                #pragma unroll
                for (int w = 0; w < 4; ++w) rem[w] |= masks[i * 4 + w];
            }
        }
        s_nv = cnt;
        #pragma unroll
        for (int w = 0; w < 4; ++w) s_keep[w] = kp[w];
    }
    __syncthreads();

    // stable partition: src[rank] = original index of rank-th kept box
    for (int r = tid; r < nsel; r += nt) {
        if ((s_keep[r >> 5] >> (r & 31)) & 1u) {
            int rank = 0;
            for (int w = 0; w < (r >> 5); ++w) rank += __popc(s_keep[w]);
            rank += __popc(s_keep[r >> 5] & ((1u << (r & 31)) - 1u));
            src[rank] = r;
        }
    }
    __syncthreads();
    int nv = s_nv;
    for (int o = tid; o < MAXT; o += nt) {
        float v0 = 0.f, v1 = 0.f, v2 = 0.f, v3 = 0.f, vs = 0.f, vc = 0.f;
        if (o < nv) {
            int i = src[o];
            v0 = ry1[i]; v1 = rx1[i]; v2 = ry2[i]; v3 = rx2[i];
            vs = rsc[i]; vc = rcl[i];
        }
        float* fb = out + (size_t)b * MAXT * 4;
        fb[o * 4 + 0] = v0; fb[o * 4 + 1] = v1; fb[o * 4 + 2] = v2; fb[o * 4 + 3] = v3;
        out[BATCH * MAXT * 4 + b * MAXT + o] = vs;
        out[BATCH * MAXT * 4 + BATCH * MAXT + b * MAXT + o] = vc;
    }
    if (tid == 0) out[BATCH * MAXT * 4 + 2 * BATCH * MAXT + b] = (float)nv;
}

// ---------------- launch ----------------
extern "C" void kernel_launch(void* const* d_in, const int* in_sizes, int n_in,
                              void* d_out, int out_size) {
    const float* ycls = nullptr; const float* ybbox = nullptr; const float* anchors = nullptr;
    const int* ohs = nullptr; const int* ows = nullptr;
    for (int i = 0; i < n_in; ++i) {
        long long s = in_sizes[i];
        if (s == (long long)BATCH * NA * NC)      ycls    = (const float*)d_in[i];
        else if (s == (long long)BATCH * NA * 4)  ybbox   = (const float*)d_in[i];
        else if (s == (long long)NA * 4)          anchors = (const float*)d_in[i];
        else if (s == BATCH) { if (!ohs) ohs = (const int*)d_in[i]; else ows = (const int*)d_in[i]; }
    }
    float* out = (float*)d_out;

    k_zero<<<(BATCH * NC + 255) / 256, 256>>>();

    long long total4 = (long long)BATCH * NA * NC / 4;
    int nblk = (int)((total4 + 255) / 256);
    k_filter<<<nblk, 256>>>(ycls);

    dim3 g2(NC, BATCH);
    k_classnms<<<g2, 512, K2_SMEM>>>(ybbox, anchors);

    k_final<<<BATCH, 512, K3_SMEM>>>(ohs, ows, out);
}

// round 5
// speedup vs baseline: 5.5299x; 5.5299x over previous
#include <cuda_runtime.h>
#include <math.h>

#define BATCH 8
#define NA 49104
#define NC 80
#define KPRE 256
#define CAP 12288
#define CCAP 2048
#define MAXT 100
#define NEGV -1000000000.0f
#define TILE_A 96
#define NTILES 512            // ceil(49104/96)
#define CNT_STRIDE 64         // u32 stride (256B) between counters -> distinct LTS lines
#define KCAP 8192             // per-batch kept-list capacity (max possible = 80*100)

// ---------------- device scratch (no allocations allowed) ----------------
__device__ unsigned long long g_cand[(size_t)BATCH * NC * CAP]; // ~63 MB (L2-resident working set)
__device__ unsigned int g_cntp[BATCH * NC * CNT_STRIDE];        // padded per-(b,c) counters
__device__ unsigned int g_bcnt[BATCH * CNT_STRIDE];             // padded per-batch kept counters
__device__ unsigned long long g_kkey[BATCH * KCAP];             // kept keys (score | ~flat | pos)
__device__ float4 g_kbox[BATCH * KCAP];                         // kept boxes

// ---------------- K0: zero counters ----------------
__global__ void k_zero() {
    int t = blockIdx.x * blockDim.x + threadIdx.x;
    if (t < BATCH * NC * CNT_STRIDE) g_cntp[t] = 0;
    if (t < BATCH * CNT_STRIDE) g_bcnt[t] = 0;
}

// ---------------- K1: tiled filter, smem aggregation, 1 atomic per (block,class) ----------------
__global__ void __launch_bounds__(256) k_filter(const float* __restrict__ ycls) {
    __shared__ unsigned int  bs[NC * TILE_A];   // score bits per class bucket
    __shared__ unsigned char ba[NC * TILE_A];   // local anchor per class bucket
    __shared__ int scnt[NC];

    int tid = threadIdx.x;
    int b = blockIdx.y;
    int a0 = blockIdx.x * TILE_A;
    int na = NA - a0; if (na > TILE_A) na = TILE_A;

    for (int i = tid; i < NC; i += 256) scnt[i] = 0;
    __syncthreads();

    const float4* src = reinterpret_cast<const float4*>(ycls + ((size_t)b * NA + a0) * NC);
    int nvec = na * (NC / 4);
    for (int v = tid; v < nvec; v += 256) {
        float4 f = src[v];
        int e = v * 4;
        int la = e / NC;
        int c  = e % NC;
        float xs[4] = {f.x, f.y, f.z, f.w};
        #pragma unroll
        for (int k = 0; k < 4; ++k) {
            float x = xs[k];
            if (x > -2.95f) {                       // sigmoid(x) > 0.05 prefilter (slightly wide)
                float s = 1.0f / (1.0f + expf(-x));
                if (s > 0.05f) {
                    int cc = c + k;
                    int idx = atomicAdd(&scnt[cc], 1);
                    bs[cc * TILE_A + idx] = __float_as_uint(s);
                    ba[cc * TILE_A + idx] = (unsigned char)la;
                }
            }
        }
    }
    __syncthreads();

    // flush buckets: warp w handles classes w, w+8, ...
    int w = tid >> 5, lane = tid & 31;
    for (int c = w; c < NC; c += 8) {
        int ncx = scnt[c];
        if (ncx == 0) continue;
        int li = b * NC + c;
        int base = 0;
        if (lane == 0) base = (int)atomicAdd(&g_cntp[li * CNT_STRIDE], (unsigned)ncx);
        base = __shfl_sync(0xffffffffu, base, 0);
        for (int j = lane; j < ncx; j += 32) {
            int p = base + j;
            if (p < CAP) {
                unsigned sb = bs[c * TILE_A + j];
                unsigned a  = (unsigned)(a0 + ba[c * TILE_A + j]);
                g_cand[(size_t)li * CAP + p] =
                    ((unsigned long long)sb << 32) | (unsigned long long)(0xFFFFFFFFu - a);
            }
        }
    }
}

// ---------------- K2: per-(b,c) exact top-256 + greedy NMS + compact kept output ----------------
// dynamic smem layout:
//   [0      , 16384) cand   (2048 x u64)
//   [16384  , 32768) hist   (4096 x u32)   -- reused later for IoU masks (8 KB)
//   [32768  , 34816) chunk  (512 x u32)
//   [34816  , 40960) by1,bx1,by2,bx2,bar,bsc (6 x 256 f32)
#define K2_SMEM 40960

__global__ void __launch_bounds__(512) k_classnms(const float* __restrict__ ybbox,
                                                  const float* __restrict__ anchors) {
    extern __shared__ unsigned char smem_raw[];
    unsigned long long* cand = (unsigned long long*)smem_raw;
    unsigned int* hist  = (unsigned int*)(smem_raw + 16384);
    unsigned int* chunk = (unsigned int*)(smem_raw + 32768);
    float* by1 = (float*)(smem_raw + 34816);
    float* bx1 = by1 + 256; float* by2 = bx1 + 256; float* bx2 = by2 + 256;
    float* bar = bx2 + 256; float* bsc = bar + 256;
    unsigned int* masks = (unsigned int*)(smem_raw + 16384); // overlaps hist (dead by then)

    __shared__ int s_cb, s_sure, s_cnt, s_base;
    __shared__ unsigned int s_keep[8];

    int tid = threadIdx.x, nt = blockDim.x;
    int c = blockIdx.x, b = blockIdx.y;
    int li = b * NC + c;
    int n = (int)g_cntp[li * CNT_STRIDE]; if (n > CAP) n = CAP;
    const unsigned long long* list = g_cand + (size_t)li * CAP;

    // --- level-1 histogram on top 12 bits of score float ---
    for (int i = tid; i < 4096; i += nt) hist[i] = 0;
    __syncthreads();
    for (int i = tid; i < n; i += nt)
        atomicAdd(&hist[(unsigned)(list[i] >> 52)], 1u);
    __syncthreads();
    if (tid < 512) {
        unsigned s = 0; int base = tid * 8;
        #pragma unroll
        for (int k = 0; k < 8; ++k) s += hist[base + k];
        chunk[tid] = s;
    }
    __syncthreads();
    if (tid == 0) {
        int acc = 0, cb = 0, sure = 0;
        for (int ch = 511; ch >= 0; --ch) {
            unsigned cs = chunk[ch];
            if (acc + (int)cs < KPRE) { acc += (int)cs; continue; }
            for (int bin = ch * 8 + 7;; --bin) {
                unsigned h = hist[bin];
                if (acc + (int)h >= KPRE) { cb = bin; sure = acc; break; }
                acc += (int)h;
            }
            break;
        }
        s_cb = cb; s_sure = sure; s_cnt = 0;
    }
    __syncthreads();
    int cb = s_cb;
    for (int i = tid; i < n; i += nt) {
        unsigned long long key = list[i];
        if ((int)(unsigned)(key >> 52) >= cb) {
            int pos = atomicAdd(&s_cnt, 1);
            if (pos < CCAP) cand[pos] = key;
        }
    }
    __syncthreads();

    if (s_cnt > CCAP) {   // refine inside boundary bin (statistically never for this data)
        int sure = s_sure;
        for (int i = tid; i < 4096; i += nt) hist[i] = 0;
        __syncthreads();
        for (int i = tid; i < n; i += nt) {
            unsigned long long key = list[i];
            if ((int)(unsigned)(key >> 52) == cb)
                atomicAdd(&hist[(unsigned)(key >> 40) & 0xFFFu], 1u);
        }
        __syncthreads();
        if (tid < 512) {
            unsigned s = 0; int base = tid * 8;
            #pragma unroll
            for (int k = 0; k < 8; ++k) s += hist[base + k];
            chunk[tid] = s;
        }
        __syncthreads();
        if (tid == 0) {
            int need = KPRE - sure; if (need < 1) need = 1;
            int acc = 0, cb2 = 0;
            for (int ch = 511; ch >= 0; --ch) {
                unsigned cs = chunk[ch];
                if (acc + (int)cs < need) { acc += (int)cs; continue; }
                for (int bin = ch * 8 + 7;; --bin) {
                    unsigned h = hist[bin];
                    if (acc + (int)h >= need) { cb2 = bin; break; }
                    acc += (int)h;
                }
                break;
            }
            s_cb = cb2; s_cnt = 0;
        }
        __syncthreads();
        int cb2 = s_cb;
        for (int i = tid; i < n; i += nt) {
            unsigned long long key = list[i];
            int bin = (int)(unsigned)(key >> 52);
            if (bin > cb || (bin == cb && (int)((unsigned)(key >> 40) & 0xFFFu) >= cb2)) {
                int pos = atomicAdd(&s_cnt, 1);
                if (pos < CCAP) cand[pos] = key;
            }
        }
        __syncthreads();
    }

    int total = min(s_cnt, CCAP);
    // --- bitonic sort descending on (score, ~anchor) keys ---
    if (total > 1) {
        int n2 = 1; while (n2 < total) n2 <<= 1;
        for (int i = tid; i < n2; i += nt) if (i >= total) cand[i] = 0ull;
        __syncthreads();
        for (int k = 2; k <= n2; k <<= 1)
            for (int j = k >> 1; j > 0; j >>= 1) {
                for (int i = tid; i < n2; i += nt) {
                    int ixj = i ^ j;
                    if (ixj > i) {
                        unsigned long long x = cand[i], y = cand[ixj];
                        bool up = ((i & k) == 0);
                        if (up ? (x < y) : (x > y)) { cand[i] = y; cand[ixj] = x; }
                    }
                }
                __syncthreads();
            }
    }
    int m = min(total, KPRE);

    // --- decode boxes for top-m ---
    for (int r = tid; r < m; r += nt) {
        unsigned long long key = cand[r];
        unsigned a = 0xFFFFFFFFu - (unsigned)(key & 0xFFFFFFFFull);
        float sc = __uint_as_float((unsigned)(key >> 32));
        float4 an  = reinterpret_cast<const float4*>(anchors)[a];
        float4 rel = reinterpret_cast<const float4*>(ybbox)[(size_t)b * NA + a];
        float ha = an.z - an.x, wa = an.w - an.y;
        float cya = an.x + 0.5f * ha, cxa = an.y + 0.5f * wa;
        float cy = cya + rel.x * ha, cx = cxa + rel.y * wa;
        float h = ha * expf(rel.z), w = wa * expf(rel.w);
        float y1 = cy - 0.5f * h, x1 = cx - 0.5f * w;
        float y2 = cy + 0.5f * h, x2 = cx + 0.5f * w;
        by1[r] = y1; bx1[r] = x1; by2[r] = y2; bx2[r] = x2;
        bar[r] = (y2 - y1) * (x2 - x1);
        bsc[r] = sc;
    }
    __syncthreads();

    // --- parallel IoU bitmask build (j > i only) ---
    for (int idx = tid; idx < m * 8; idx += nt) {
        int i = idx >> 3, w = idx & 7;
        float iy1 = by1[i], ix1 = bx1[i], iy2 = by2[i], ix2 = bx2[i], ia = bar[i];
        unsigned bits = 0;
        int j0 = w * 32;
        #pragma unroll 4
        for (int q = 0; q < 32; ++q) {
            int j = j0 + q;
            if (j > i && j < m) {
                float ih = fmaxf(fminf(iy2, by2[j]) - fmaxf(iy1, by1[j]), 0.0f);
                float iw = fmaxf(fminf(ix2, bx2[j]) - fmaxf(ix1, bx1[j]), 0.0f);
                float inter = ih * iw;
                float iou = inter / (ia + bar[j] - inter + 1e-8f);
                if (iou > 0.5f) bits |= (1u << q);
            }
        }
        masks[i * 8 + w] = bits;
    }
    __syncthreads();

    // --- serial greedy walk (thread 0), cap 100 keeps, suppression uncapped ---
    if (tid == 0) {
        unsigned rem[8] = {0,0,0,0,0,0,0,0};
        unsigned kp[8]  = {0,0,0,0,0,0,0,0};
        int cnt = 0;
        for (int i = 0; i < m; ++i) {
            if (!((rem[i >> 5] >> (i & 31)) & 1u)) {
                if (cnt < MAXT) kp[i >> 5] |= (1u << (i & 31));
                cnt++;
                #pragma unroll
                for (int w = 0; w < 8; ++w) rem[w] |= masks[i * 8 + w];
            }
        }
        int kc = 0;
        #pragma unroll
        for (int w = 0; w < 8; ++w) { s_keep[w] = kp[w]; kc += __popc(kp[w]); }
        s_base = (int)atomicAdd(&g_bcnt[b * CNT_STRIDE], (unsigned)kc);
    }
    __syncthreads();

    // --- write compact kept entries (key encodes score | ~flat | pos) ---
    int base = s_base;
    for (int r = tid; r < m; r += nt) {
        if ((s_keep[r >> 5] >> (r & 31)) & 1u) {
            int rank = 0;
            for (int w = 0; w < (r >> 5); ++w) rank += __popc(s_keep[w]);
            rank += __popc(s_keep[r >> 5] & ((1u << (r & 31)) - 1u));
            int pos = base + rank;                    // < 8000 always (<=100/class * 80)
            unsigned flat = (unsigned)(c * KPRE + r); // reference flat index
            unsigned long long key =
                ((unsigned long long)__float_as_uint(bsc[r]) << 32) |
                ((unsigned long long)(0x7FFFu - flat) << 13) |
                (unsigned long long)pos;
            g_kkey[b * KCAP + pos] = key;
            g_kbox[b * KCAP + pos] = make_float4(by1[r], bx1[r], by2[r], bx2[r]);
        }
    }
}

// ---------------- K3: per-batch top-100 + NMS@0.7 + stable partition ----------------
// dynamic smem layout:
//   [0      , 16384) cand (2048 x u64)
//   [16384  , 32768) hist (4096 x u32) -- later reused: masks (2 KB) + src (0.5 KB)
//   [32768  , 34816) chunk
//   [34816  , 38400) ry1,rx1,ry2,rx2,rar,rsc,rcl (7 x 128 f32)
#define K3_SMEM 38400

__global__ void __launch_bounds__(512) k_final(const int* __restrict__ ohs,
                                               const int* __restrict__ ows,
                                               float* __restrict__ out) {
    extern __shared__ unsigned char smem_raw[];
    unsigned long long* cand = (unsigned long long*)smem_raw;
    unsigned int* hist  = (unsigned int*)(smem_raw + 16384);
    unsigned int* chunk = (unsigned int*)(smem_raw + 32768);
    float* ry1 = (float*)(smem_raw + 34816);
    float* rx1 = ry1 + 128; float* ry2 = rx1 + 128; float* rx2 = ry2 + 128;
    float* rar = rx2 + 128; float* rsc = rar + 128; float* rcl = rsc + 128;
    unsigned int* masks = (unsigned int*)(smem_raw + 16384);        // 128*4 u32
    int* src = (int*)(smem_raw + 16384 + 2048);                     // 128 ints

    __shared__ int s_cb, s_sure, s_cnt, s_nv;
    __shared__ unsigned int s_keep[4];

    int tid = threadIdx.x, nt = blockDim.x;
    int b = blockIdx.x;
    int nb = (int)g_bcnt[b * CNT_STRIDE];           // <= 8000 structurally
    const unsigned long long* klist = g_kkey + (size_t)b * KCAP;

    int total;
    if (nb <= CCAP) {
        // fast path: load the whole kept list
        for (int i = tid; i < nb; i += nt) cand[i] = klist[i];
        total = nb;
        __syncthreads();
    } else {
        // hist-select path (rare): select ~top-100 by score bins
        for (int i = tid; i < 4096; i += nt) hist[i] = 0;
        __syncthreads();
        for (int i = tid; i < nb; i += nt)
            atomicAdd(&hist[(unsigned)(klist[i] >> 52)], 1u);
        __syncthreads();
        if (tid < 512) {
            unsigned s = 0; int base = tid * 8;
            #pragma unroll
            for (int k = 0; k < 8; ++k) s += hist[base + k];
            chunk[tid] = s;
        }
        __syncthreads();
        if (tid == 0) {
            int acc = 0, cb = 0, sure = 0;
            for (int ch = 511; ch >= 0; --ch) {
                unsigned cs = chunk[ch];
                if (acc + (int)cs < MAXT) { acc += (int)cs; continue; }
                for (int bin = ch * 8 + 7;; --bin) {
                    unsigned h = hist[bin];
                    if (acc + (int)h >= MAXT) { cb = bin; sure = acc; break; }
                    acc += (int)h;
                }
                break;
            }
            s_cb = cb; s_sure = sure; s_cnt = 0;
        }
        __syncthreads();
        int cb = s_cb;
        for (int i = tid; i < nb; i += nt) {
            unsigned long long key = klist[i];
            if ((int)(unsigned)(key >> 52) >= cb) {
                int pos = atomicAdd(&s_cnt, 1);
                if (pos < CCAP) cand[pos] = key;
            }
        }
        __syncthreads();
        if (s_cnt > CCAP) {   // refine (statistically never)
            int sure = s_sure;
            for (int i = tid; i < 4096; i += nt) hist[i] = 0;
            __syncthreads();
            for (int i = tid; i < nb; i += nt) {
                unsigned long long key = klist[i];
                if ((int)(unsigned)(key >> 52) == cb)
                    atomicAdd(&hist[(unsigned)(key >> 40) & 0xFFFu], 1u);
            }
            __syncthreads();
            if (tid < 512) {
                unsigned s = 0; int base = tid * 8;
                #pragma unroll
                for (int k = 0; k < 8; ++k) s += hist[base + k];
                chunk[tid] = s;
            }
            __syncthreads();
            if (tid == 0) {
                int need = MAXT - sure; if (need < 1) need = 1;
                int acc = 0, cb2 = 0;
                for (int ch = 511; ch >= 0; --ch) {
                    unsigned cs = chunk[ch];
                    if (acc + (int)cs < need) { acc += (int)cs; continue; }
                    for (int bin = ch * 8 + 7;; --bin) {
                        unsigned h = hist[bin];
                        if (acc + (int)h >= need) { cb2 = bin; break; }
                        acc += (int)h;
                    }
                    break;
                }
                s_cb = cb2; s_cnt = 0;
            }
            __syncthreads();
            int cb2 = s_cb;
            for (int i = tid; i < nb; i += nt) {
                unsigned long long key = klist[i];
                int bin = (int)(unsigned)(key >> 52);
                if (bin > cb || (bin == cb && (int)((unsigned)(key >> 40) & 0xFFFu) >= cb2)) {
                    int pos = atomicAdd(&s_cnt, 1);
                    if (pos < CCAP) cand[pos] = key;
                }
            }
            __syncthreads();
        }
        total = min(s_cnt, CCAP);
    }

    if (total > 1) {
        int n2 = 1; while (n2 < total) n2 <<= 1;
        for (int i = tid; i < n2; i += nt) if (i >= total) cand[i] = 0ull;
        __syncthreads();
        for (int k = 2; k <= n2; k <<= 1)
            for (int j = k >> 1; j > 0; j >>= 1) {
                for (int i = tid; i < n2; i += nt) {
                    int ixj = i ^ j;
                    if (ixj > i) {
                        unsigned long long x = cand[i], y = cand[ixj];
                        bool up = ((i & k) == 0);
                        if (up ? (x < y) : (x > y)) { cand[i] = y; cand[ixj] = x; }
                    }
                }
                __syncthreads();
            }
    }
    int nsel = min(total, MAXT);

    float fh = (float)ohs[b], fw = (float)ows[b];
    float rh = fh / 512.0f, rw = fw / 512.0f;
    for (int r = tid; r < nsel; r += nt) {
        unsigned long long key = cand[r];
        int pos = (int)(key & 0x1FFFull);
        unsigned flat = 0x7FFFu - (unsigned)((key >> 13) & 0x7FFFull);
        float sc = __uint_as_float((unsigned)(key >> 32));
        float4 bx = g_kbox[(size_t)b * KCAP + pos];
        float y1 = fminf(fmaxf(bx.x * rh, 0.0f), fh);
        float x1 = fminf(fmaxf(bx.y * rw, 0.0f), fw);
        float y2 = fminf(fmaxf(bx.z * rh, 0.0f), fh);
        float x2 = fminf(fmaxf(bx.w * rw, 0.0f), fw);
        ry1[r] = y1; rx1[r] = x1; ry2[r] = y2; rx2[r] = x2;
        rar[r] = (y2 - y1) * (x2 - x1);
        rsc[r] = sc;
        rcl[r] = (float)(flat >> 8);   // flat = class*256 + rank
    }
    __syncthreads();

    for (int idx = tid; idx < nsel * 4; idx += nt) {
        int i = idx >> 2, w = idx & 3;
        float iy1 = ry1[i], ix1 = rx1[i], iy2 = ry2[i], ix2 = rx2[i], ia = rar[i];
        unsigned bits = 0;
        int j0 = w * 32;
        #pragma unroll 4
        for (int q = 0; q < 32; ++q) {
            int j = j0 + q;
            if (j > i && j < nsel) {
                float ih = fmaxf(fminf(iy2, ry2[j]) - fmaxf(iy1, ry1[j]), 0.0f);
                float iw = fmaxf(fminf(ix2, rx2[j]) - fmaxf(ix1, rx1[j]), 0.0f);
                float inter = ih * iw;
                float iou = inter / (ia + rar[j] - inter + 1e-8f);
                if (iou > 0.7f) bits |= (1u << q);
            }
        }
        masks[i * 4 + w] = bits;
    }
    __syncthreads();
    if (tid == 0) {
        unsigned rem[4] = {0,0,0,0}, kp[4] = {0,0,0,0};
        int cnt = 0;
        for (int i = 0; i < nsel; ++i) {
            if (!((rem[i >> 5] >> (i & 31)) & 1u)) {
                kp[i >> 5] |= (1u << (i & 31));
                cnt++;
                #pragma unroll
                for (int w = 0; w < 4; ++w) rem[w] |= masks[i * 4 + w];
            }
        }
        s_nv = cnt;
        #pragma unroll
        for (int w = 0; w < 4; ++w) s_keep[w] = kp[w];
    }
    __syncthreads();

    // stable partition: src[rank] = original index of rank-th kept box
    for (int r = tid; r < nsel; r += nt) {
        if ((s_keep[r >> 5] >> (r & 31)) & 1u) {
            int rank = 0;
            for (int w = 0; w < (r >> 5); ++w) rank += __popc(s_keep[w]);
            rank += __popc(s_keep[r >> 5] & ((1u << (r & 31)) - 1u));
            src[rank] = r;
        }
    }
    __syncthreads();
    int nv = s_nv;
    for (int o = tid; o < MAXT; o += nt) {
        float v0 = 0.f, v1 = 0.f, v2 = 0.f, v3 = 0.f, vs = 0.f, vc = 0.f;
        if (o < nv) {
            int i = src[o];
            v0 = ry1[i]; v1 = rx1[i]; v2 = ry2[i]; v3 = rx2[i];
            vs = rsc[i]; vc = rcl[i];
        }
        float* fb = out + (size_t)b * MAXT * 4;
        fb[o * 4 + 0] = v0; fb[o * 4 + 1] = v1; fb[o * 4 + 2] = v2; fb[o * 4 + 3] = v3;
        out[BATCH * MAXT * 4 + b * MAXT + o] = vs;
        out[BATCH * MAXT * 4 + BATCH * MAXT + b * MAXT + o] = vc;
    }
    if (tid == 0) out[BATCH * MAXT * 4 + 2 * BATCH * MAXT + b] = (float)nv;
}

// ---------------- launch ----------------
extern "C" void kernel_launch(void* const* d_in, const int* in_sizes, int n_in,
                              void* d_out, int out_size) {
    const float* ycls = nullptr; const float* ybbox = nullptr; const float* anchors = nullptr;
    const int* ohs = nullptr; const int* ows = nullptr;
    for (int i = 0; i < n_in; ++i) {
        long long s = in_sizes[i];
        if (s == (long long)BATCH * NA * NC)      ycls    = (const float*)d_in[i];
        else if (s == (long long)BATCH * NA * 4)  ybbox   = (const float*)d_in[i];
        else if (s == (long long)NA * 4)          anchors = (const float*)d_in[i];
        else if (s == BATCH) { if (!ohs) ohs = (const int*)d_in[i]; else ows = (const int*)d_in[i]; }
    }
    float* out = (float*)d_out;

    int nz = BATCH * NC * CNT_STRIDE;
    k_zero<<<(nz + 255) / 256, 256>>>();

    dim3 g1(NTILES, BATCH);
    k_filter<<<g1, 256>>>(ycls);

    dim3 g2(NC, BATCH);
    k_classnms<<<g2, 512, K2_SMEM>>>(ybbox, anchors);

    k_final<<<BATCH, 512, K3_SMEM>>>(ohs, ows, out);
}